// round 10
// baseline (speedup 1.0000x reference)
#include <cuda_runtime.h>
#include <cstdint>

// Problem constants
#define Bn 16
#define Jn 16
#define Cn 64
#define HWn 65536                 // 256*256
#define SPLIT 4
#define CHUNK (HWn / SPLIT)       // 16384 floats per split-block
#define NPART (Bn * Jn * SPLIT)   // 1024 blocks
#define BLKS_PER_B (Jn * SPLIT)   // 64 blocks feed each batch
#define QPT (CHUNK / 4 / 256)     // 16 float4s per thread
#define OBATCH 4                  // float4s in flight per thread (reg cap)

#define NEG_INF (-3.4028235e38f)

// Scratch (device globals: allocation-free). g_count starts zeroed; each
// finalizer resets its slot so graph replays are deterministic.
__device__ float g_pval[NPART];
__device__ int   g_pidx[NPART];
__device__ int   g_count[Bn];

// ---------------------------------------------------------------------------
// Fused kernel: streaming max scan (reg-capped batches) -> winning-warp index
// rescan -> last-block-per-batch finalize. grid = 1024 blocks, 256 threads.
// ---------------------------------------------------------------------------
__global__ __launch_bounds__(256) void fused_labelloss_kernel(
    const float* __restrict__ heatmap,
    const float* __restrict__ pred,
    const float* __restrict__ gt,
    float* __restrict__ out)
{
    const int blk = blockIdx.x;
    const int bj  = blk / SPLIT;         // b*Jn + j
    const int s   = blk % SPLIT;
    const int b   = bj / Jn;
    const int t   = threadIdx.x;
    const int wid = t >> 5, lid = t & 31;

    const float4* __restrict__ src = reinterpret_cast<const float4*>(
        heatmap + (size_t)bj * HWn + (size_t)s * CHUNK);

    __shared__ float swm[8];
    __shared__ float s_bmax;
    __shared__ int   s_bidx;
    __shared__ int   s_last;

    if (t == 0) s_bidx = 0x7fffffff;

    // ---- Pass 1: pure running max; OBATCH float4 loads in flight ----------
    // #pragma unroll 1 stops ptxas from front-batching all 16 loads (which
    // costs 64 regs and collapses occupancy -- measured R5/R9).
    float m = NEG_INF;
    #pragma unroll 1
    for (int o = 0; o < QPT / OBATCH; ++o) {
        const int p = t + o * (OBATCH * 256);
        const float4 v0 = __ldg(&src[p]);
        const float4 v1 = __ldg(&src[p + 256]);
        const float4 v2 = __ldg(&src[p + 512]);
        const float4 v3 = __ldg(&src[p + 768]);
        const float m0 = fmaxf(fmaxf(v0.x, v0.y), fmaxf(v0.z, v0.w));
        const float m1 = fmaxf(fmaxf(v1.x, v1.y), fmaxf(v1.z, v1.w));
        const float m2 = fmaxf(fmaxf(v2.x, v2.y), fmaxf(v2.z, v2.w));
        const float m3 = fmaxf(fmaxf(v3.x, v3.y), fmaxf(v3.z, v3.w));
        m = fmaxf(m, fmaxf(fmaxf(m0, m1), fmaxf(m2, m3)));
    }

    // warp max (xor butterfly: all lanes get warp max)
    #pragma unroll
    for (int off = 16; off > 0; off >>= 1)
        m = fmaxf(m, __shfl_xor_sync(0xffffffff, m, off));

    if (lid == 0) swm[wid] = m;
    __syncthreads();

    if (t < 32) {
        float mm = (t < 8) ? swm[t] : NEG_INF;
        #pragma unroll
        for (int off = 4; off > 0; off >>= 1)
            mm = fmaxf(mm, __shfl_xor_sync(0xffffffff, mm, off));
        if (t == 0) s_bmax = mm;
    }
    __syncthreads();

    const float bmax = s_bmax;

    // ---- Pass 2: only winning warp(s) rescan their slice (L1/L2-hot) -------
    // atomicMin over flat index = exact first-occurrence argmax semantics.
    if (swm[wid] == bmax) {
        #pragma unroll 1
        for (int it = 0; it < QPT; ++it) {
            const int p = t + it * 256;
            const float4 v = __ldg(&src[p]);
            const int base = s * CHUNK + p * 4;
            if (v.x == bmax) atomicMin(&s_bidx, base + 0);
            if (v.y == bmax) atomicMin(&s_bidx, base + 1);
            if (v.z == bmax) atomicMin(&s_bidx, base + 2);
            if (v.w == bmax) atomicMin(&s_bidx, base + 3);
        }
    }
    __syncthreads();

    // ---- Publish partial; 64th arriver per batch finalizes -----------------
    if (t == 0) {
        g_pval[bj * SPLIT + s] = bmax;
        g_pidx[bj * SPLIT + s] = s_bidx;
        __threadfence();
        const int prev = atomicAdd(&g_count[b], 1);
        s_last = (prev == BLKS_PER_B - 1) ? 1 : 0;
    }
    __syncthreads();

    if (!s_last) return;

    // ------------------- Finalize batch b: gather + MSE ---------------------
    __shared__ int s_idx[Jn];

    if (t < Jn) {
        const int base = (b * Jn + t) * SPLIT;
        float bv = NEG_INF;
        int   bi = 0x7fffffff;
        #pragma unroll
        for (int k = 0; k < SPLIT; ++k) {
            const float v = __ldcg(&g_pval[base + k]);
            const int   i = __ldcg(&g_pidx[base + k]);
            if (v > bv || (v == bv && i < bi)) { bv = v; bi = i; }
        }
        s_idx[t] = bi;
    }
    __syncthreads();

    // J*C = 1024 gathered elements, 256 threads -> 4 each
    float acc = 0.0f;
    #pragma unroll
    for (int it = 0; it < (Jn * Cn) / 256; ++it) {
        const int e = t + it * 256;
        const int j = e >> 6;        // /64
        const int c = e & 63;        // %64
        const int idx = s_idx[j];
        const float p = __ldg(&pred[((size_t)b * Cn + c) * HWn + idx]);
        const float g = __ldg(&gt[((size_t)b * Jn + j) * Cn + c]);
        const float d = p - g;
        acc += d * d;
    }

    #pragma unroll
    for (int off = 16; off > 0; off >>= 1)
        acc += __shfl_down_sync(0xffffffff, acc, off);

    __shared__ float ss[8];
    if (lid == 0) ss[wid] = acc;
    __syncthreads();
    if (t < 32) {
        acc = (lid < 8) ? ss[lid] : 0.0f;
        #pragma unroll
        for (int off = 4; off > 0; off >>= 1)
            acc += __shfl_down_sync(0xffffffff, acc, off);
        if (lid == 0) {
            out[b] = acc * (1.0f / (Jn * Cn));
            g_count[b] = 0;   // reset for next graph replay
        }
    }
}

extern "C" void kernel_launch(void* const* d_in, const int* in_sizes, int n_in,
                              void* d_out, int out_size)
{
    const float* pred    = (const float*)d_in[0];   // [B,C,H,W]
    const float* gt      = (const float*)d_in[1];   // [B,J,C]
    const float* heatmap = (const float*)d_in[2];   // [B,J,H,W]
    float* out = (float*)d_out;                     // [B]

    fused_labelloss_kernel<<<NPART, 256>>>(heatmap, pred, gt, out);
}